// round 3
// baseline (speedup 1.0000x reference)
#include <cuda_runtime.h>
#include <math.h>

// Problem constants (fixed by the reference: B=16, N=4096, Z=128)
#define BB 16
#define NN 4096
#define ZZ 128

#define THREADS 256
#define Q 16                    // preds per thread: 256*16 = 4096 = ALL preds of the batch
#define GSPLIT 8                // gt splits per batch
#define GTS (NN / GSPLIT)       // 512 gts per CTA
#define NCTAS (BB * GSPLIT)     // 128
#define NWARPS (THREADS / 32)   // 8

__device__ float g_rowmin[NCTAS * NN];  // [cta][pred] partial row-mins (2MB)
__device__ float g_colsum[NCTAS];       // per-CTA complete col-min sums
__device__ float g_part2[NCTAS];        // finish-kernel CTA partials
__device__ int   g_count = 0;

// FFMA with immediate 1.0 multiplier: rt_SMSP=1 (2x tput vs 3-reg FFMA/FADD)
__device__ __forceinline__ float fma_i1(float a, float c) {
    float d;
    asm("fma.rn.f32 %0, %1, 0f3F800000, %2;" : "=f"(d) : "f"(a), "f"(c));
    return d;
}

// Each CTA: batch b, gt range [split*512, split*512+512), ALL 4096 preds.
// Every evaluated distance t = ||g||^2 + ||p||^2 - 2 g.p = P[j, q] feeds BOTH
// the per-pred row-min (registers, partial over this gt split) and the per-gt
// col-min (complete: all 4096 preds live in this CTA's registers).
// This halves the distance evaluations vs the two-direction formulation.
__global__ __launch_bounds__(THREADS, 1)
void chamfer_main(const float* __restrict__ preds,
                  const float* __restrict__ gts)
{
    __shared__ float4 sg[GTS];             // 8KB: (-2gx, -2gy, -2gz, ||g||^2)
    __shared__ float  scol[NWARPS * GTS];  // 16KB: per-warp col-mins (race-free)
    __shared__ float  red[THREADS];

    const int split = blockIdx.x;
    const int b     = blockIdx.y;
    const float* __restrict__ pb = preds + b * 3 * NN;
    const float* __restrict__ gb = gts   + b * 3 * NN;

    const int tid  = threadIdx.x;
    const int wid  = tid >> 5;

    // Stage this CTA's gts (coalesced per-channel loads, pre-scale by -2)
    for (int i = tid; i < GTS; i += THREADS) {
        const int n = split * GTS + i;
        const float x0 = gb[n];
        const float x1 = gb[NN + n];
        const float x2 = gb[2 * NN + n];
        sg[i] = make_float4(-2.0f * x0, -2.0f * x1, -2.0f * x2,
                            x0 * x0 + x1 * x1 + x2 * x2);
    }

    // Load this thread's 16 preds into registers
    float px[Q], py[Q], pz[Q], rp[Q], mn[Q];
#pragma unroll
    for (int q = 0; q < Q; q++) {
        const int m = tid + q * THREADS;
        px[q] = pb[m];
        py[q] = pb[NN + m];
        pz[q] = pb[2 * NN + m];
        rp[q] = px[q] * px[q] + py[q] * py[q] + pz[q] * pz[q];
        mn[q] = 3.4e38f;
    }
    __syncthreads();

    // Main sweep: each warp visits every gt j once.
#pragma unroll 2
    for (int j = 0; j < GTS; j++) {
        const float4 g = sg[j];            // broadcast LDS.128
        float cm = 3.4e38f;
#pragma unroll
        for (int q = 0; q < Q; q++) {
            // t = ||g||^2 + ||p||^2 - 2 g.p   (seed via imm-FFMA, then 3 FFMA)
            float t = fma_i1(g.w, rp[q]);
            t = fmaf(g.x, px[q], fmaf(g.y, py[q], fmaf(g.z, pz[q], t)));
            mn[q] = fminf(mn[q], t);       // row-min (per pred)
            cm    = fminf(cm, t);          // col candidate (this lane's 16 preds)
        }
        // Warp min over 32 lanes -> min over this warp's 512 preds
#pragma unroll
        for (int off = 16; off > 0; off >>= 1)
            cm = fminf(cm, __shfl_xor_sync(0xFFFFFFFFu, cm, off));
        scol[wid * GTS + j] = cm;          // all lanes same value/address
    }

    // Emit partial row-mins (coalesced)
    const int cta = b * GSPLIT + split;
#pragma unroll
    for (int q = 0; q < Q; q++)
        g_rowmin[cta * NN + tid + q * THREADS] = mn[q];

    __syncthreads();

    // Cross-warp col-min reduce + sum over this CTA's 512 gts
    float s = 0.0f;
    for (int i = tid; i < GTS; i += THREADS) {
        float c = scol[i];
#pragma unroll
        for (int w = 1; w < NWARPS; w++)
            c = fminf(c, scol[w * GTS + i]);
        s += c;
    }
    red[tid] = s;
    __syncthreads();
    for (int off = THREADS / 2; off > 0; off >>= 1) {
        if (tid < off) red[tid] += red[tid + off];
        __syncthreads();
    }
    if (tid == 0) g_colsum[cta] = red[0];
}

// Finish: min-combine the 8 gt-split partial row-mins per pred, sum; the
// ticket-last CTA folds in the col-sums + KL and writes the scalar.
__global__ __launch_bounds__(THREADS)
void chamfer_finish(const float* __restrict__ mu,
                    const float* __restrict__ logvar,
                    float* __restrict__ out)
{
    __shared__ float red[THREADS];
    __shared__ int   slast;

    const int tid   = threadIdx.x;
    const int cta   = blockIdx.x;          // 128 CTAs
    const int b     = cta >> 3;
    const int chunk = cta & 7;
    if (tid == 0) slast = 0;

    float s = 0.0f;
#pragma unroll
    for (int k = 0; k < 2; k++) {
        const int p = chunk * 512 + tid + k * THREADS;
        float m = 3.4e38f;
#pragma unroll
        for (int sp = 0; sp < GSPLIT; sp++)
            m = fminf(m, g_rowmin[(b * GSPLIT + sp) * NN + p]);
        s += m;
    }

    red[tid] = s;
    __syncthreads();
    for (int off = THREADS / 2; off > 0; off >>= 1) {
        if (tid < off) red[tid] += red[tid + off];
        __syncthreads();
    }
    if (tid == 0) {
        g_part2[cta] = red[0];
        __threadfence();
        const int old = atomicAdd(&g_count, 1);
        if (old == NCTAS - 1) slast = 1;
    }
    __syncthreads();

    if (slast) {
        __threadfence();
        float f = 0.0f;
        volatile const float* vp2 = g_part2;
        volatile const float* vpc = g_colsum;
        for (int i = tid; i < NCTAS; i += THREADS) f += vp2[i] + vpc[i];
        for (int i = tid; i < BB * ZZ; i += THREADS) {
            const float m  = mu[i];
            const float lv = logvar[i];
            f += -0.5f * (1.0f + lv - m * m - expf(lv));
        }
        red[tid] = f;
        __syncthreads();
        for (int off = THREADS / 2; off > 0; off >>= 1) {
            if (tid < off) red[tid] += red[tid + off];
            __syncthreads();
        }
        if (tid == 0) {
            out[0] = red[0];
            g_count = 0;   // reset for next graph replay
        }
    }
}

extern "C" void kernel_launch(void* const* d_in, const int* in_sizes, int n_in,
                              void* d_out, int out_size)
{
    const float* preds  = (const float*)d_in[0];   // [16, 3, 4096]
    const float* gts    = (const float*)d_in[1];   // [16, 3, 4096]
    const float* mu     = (const float*)d_in[2];   // [16, 128]
    const float* logvar = (const float*)d_in[3];   // [16, 128]
    float* out = (float*)d_out;

    dim3 grid(GSPLIT, BB);
    chamfer_main<<<grid, THREADS>>>(preds, gts);
    chamfer_finish<<<NCTAS, THREADS>>>(mu, logvar, out);
}

// round 4
// speedup vs baseline: 1.2185x; 1.2185x over previous
#include <cuda_runtime.h>
#include <math.h>

// Problem constants (fixed by the reference: B=16, N=4096, Z=128)
#define BB 16
#define NN 4096
#define ZZ 128

#define THREADS 512
#define Q 8                     // preds per thread: 512*8 = 4096 = ALL preds of the batch
#define GSPLIT 16               // gt splits per batch
#define GTS (NN / GSPLIT)       // 256 gts per CTA
#define NCTAS (BB * GSPLIT)     // 256
#define NWARPS (THREADS / 32)   // 16

__device__ float g_rowmin[NCTAS * NN];  // [cta][pred] partial row-mins (4MB)
__device__ float g_colsum[NCTAS];       // per-CTA complete col-min sums
__device__ float g_part2[NCTAS];        // finish-kernel CTA partials
__device__ int   g_count = 0;

// FFMA with immediate 1.0 multiplier: rt_SMSP=1 (2x tput vs 3-reg FFMA/FADD)
__device__ __forceinline__ float fma_i1(float a, float c) {
    float d;
    asm("fma.rn.f32 %0, %1, 0f3F800000, %2;" : "=f"(d) : "f"(a), "f"(c));
    return d;
}

// Each CTA: batch b, gt range [split*256, +256), ALL 4096 preds in registers.
// Per eval:  t = ||g||^2 - 2 g.p           (3 FFMA, chain seeded with gw)
//   row-min: mn[q] = min(mn[q], t)          (+ rp[q] folded in once at emit)
//   col-min: cm    = min(cm, t*1.0 + rp[q]) (imm-FFMA rt=1; cm is full P)
// 7 fma-pipe cyc + 2 alu cyc per eval; every distance feeds both loss terms.
__global__ __launch_bounds__(THREADS, 2)
void chamfer_main(const float* __restrict__ preds,
                  const float* __restrict__ gts)
{
    __shared__ float4 sg[GTS];             // 4KB: (-2gx, -2gy, -2gz, ||g||^2)
    __shared__ float  scol[NWARPS * GTS];  // 16KB: per-warp col-mins (race-free)
    __shared__ float  red[THREADS];

    const int split = blockIdx.x;
    const int b     = blockIdx.y;
    const float* __restrict__ pb = preds + b * 3 * NN;
    const float* __restrict__ gb = gts   + b * 3 * NN;

    const int tid = threadIdx.x;
    const int wid = tid >> 5;

    // Stage this CTA's gts (coalesced per-channel loads, pre-scale by -2)
    for (int i = tid; i < GTS; i += THREADS) {
        const int n = split * GTS + i;
        const float x0 = gb[n];
        const float x1 = gb[NN + n];
        const float x2 = gb[2 * NN + n];
        sg[i] = make_float4(-2.0f * x0, -2.0f * x1, -2.0f * x2,
                            x0 * x0 + x1 * x1 + x2 * x2);
    }

    // This thread's 8 preds in registers
    float px[Q], py[Q], pz[Q], rp[Q], mn[Q];
#pragma unroll
    for (int q = 0; q < Q; q++) {
        const int m = tid + q * THREADS;
        px[q] = pb[m];
        py[q] = pb[NN + m];
        pz[q] = pb[2 * NN + m];
        rp[q] = px[q] * px[q] + py[q] * py[q] + pz[q] * pz[q];
        mn[q] = 3.4e38f;
    }
    __syncthreads();

    // Main sweep, 2 gts per iteration for independent shfl chains
    for (int j = 0; j < GTS; j += 2) {
        const float4 g0 = sg[j];
        const float4 g1 = sg[j + 1];
        float ca0 = 3.4e38f, cb0 = 3.4e38f;
        float ca1 = 3.4e38f, cb1 = 3.4e38f;
#pragma unroll
        for (int q = 0; q < Q; q += 2) {
            float t00 = fmaf(g0.x, px[q],   fmaf(g0.y, py[q],   fmaf(g0.z, pz[q],   g0.w)));
            float t01 = fmaf(g0.x, px[q+1], fmaf(g0.y, py[q+1], fmaf(g0.z, pz[q+1], g0.w)));
            float t10 = fmaf(g1.x, px[q],   fmaf(g1.y, py[q],   fmaf(g1.z, pz[q],   g1.w)));
            float t11 = fmaf(g1.x, px[q+1], fmaf(g1.y, py[q+1], fmaf(g1.z, pz[q+1], g1.w)));
            mn[q]   = fminf(mn[q],   fminf(t00, t10));
            mn[q+1] = fminf(mn[q+1], fminf(t01, t11));
            ca0 = fminf(ca0, fma_i1(t00, rp[q]));
            cb0 = fminf(cb0, fma_i1(t01, rp[q+1]));
            ca1 = fminf(ca1, fma_i1(t10, rp[q]));
            cb1 = fminf(cb1, fma_i1(t11, rp[q+1]));
        }
        float cm0 = fminf(ca0, cb0);
        float cm1 = fminf(ca1, cb1);
#pragma unroll
        for (int off = 16; off > 0; off >>= 1) {
            cm0 = fminf(cm0, __shfl_xor_sync(0xFFFFFFFFu, cm0, off));
            cm1 = fminf(cm1, __shfl_xor_sync(0xFFFFFFFFu, cm1, off));
        }
        scol[wid * GTS + j]     = cm0;  // all lanes same value/address
        scol[wid * GTS + j + 1] = cm1;
    }

    // Emit partial row-mins (coalesced); fold in rp here
    const int cta = b * GSPLIT + split;
#pragma unroll
    for (int q = 0; q < Q; q++)
        g_rowmin[cta * NN + tid + q * THREADS] = mn[q] + rp[q];

    __syncthreads();

    // Cross-warp col-min reduce + sum over this CTA's 256 gts
    float s = 0.0f;
    for (int i = tid; i < GTS; i += THREADS) {
        float c = scol[i];
#pragma unroll
        for (int w = 1; w < NWARPS; w++)
            c = fminf(c, scol[w * GTS + i]);
        s += c;
    }
    red[tid] = s;
    __syncthreads();
    for (int off = THREADS / 2; off > 0; off >>= 1) {
        if (tid < off) red[tid] += red[tid + off];
        __syncthreads();
    }
    if (tid == 0) g_colsum[cta] = red[0];
}

// Finish: one pred per thread, 16-way min-combine with MLP=16; ticket-last
// CTA folds col-sums + KL and writes the scalar.
__global__ __launch_bounds__(256)
void chamfer_finish(const float* __restrict__ mu,
                    const float* __restrict__ logvar,
                    float* __restrict__ out)
{
    __shared__ float red[256];
    __shared__ int   slast;

    const int tid = threadIdx.x;
    const int cta = blockIdx.x;             // 256 CTAs x 256 threads = 65536 preds
    if (tid == 0) slast = 0;

    const int pg = cta * 256 + tid;         // global pred index
    const int b  = pg >> 12;
    const int p  = pg & (NN - 1);

    float m = 3.4e38f;
#pragma unroll
    for (int sp = 0; sp < GSPLIT; sp++)
        m = fminf(m, g_rowmin[(b * GSPLIT + sp) * NN + p]);

    red[tid] = m;
    __syncthreads();
    for (int off = 128; off > 0; off >>= 1) {
        if (tid < off) red[tid] += red[tid + off];
        __syncthreads();
    }
    if (tid == 0) {
        g_part2[cta] = red[0];
        __threadfence();
        const int old = atomicAdd(&g_count, 1);
        if (old == NCTAS - 1) slast = 1;
    }
    __syncthreads();

    if (slast) {
        __threadfence();
        float f = 0.0f;
        volatile const float* vp2 = g_part2;
        volatile const float* vpc = g_colsum;
        for (int i = tid; i < NCTAS; i += 256) f += vp2[i] + vpc[i];
        for (int i = tid; i < BB * ZZ; i += 256) {
            const float mm = mu[i];
            const float lv = logvar[i];
            f += -0.5f * (1.0f + lv - mm * mm - expf(lv));
        }
        red[tid] = f;
        __syncthreads();
        for (int off = 128; off > 0; off >>= 1) {
            if (tid < off) red[tid] += red[tid + off];
            __syncthreads();
        }
        if (tid == 0) {
            out[0] = red[0];
            g_count = 0;   // reset for next graph replay
        }
    }
}

extern "C" void kernel_launch(void* const* d_in, const int* in_sizes, int n_in,
                              void* d_out, int out_size)
{
    const float* preds  = (const float*)d_in[0];   // [16, 3, 4096]
    const float* gts    = (const float*)d_in[1];   // [16, 3, 4096]
    const float* mu     = (const float*)d_in[2];   // [16, 128]
    const float* logvar = (const float*)d_in[3];   // [16, 128]
    float* out = (float*)d_out;

    dim3 grid(GSPLIT, BB);
    chamfer_main<<<grid, THREADS>>>(preds, gts);
    chamfer_finish<<<NCTAS, 256>>>(mu, logvar, out);
}